// round 8
// baseline (speedup 1.0000x reference)
#include <cuda_runtime.h>
#include <math.h>

#define NTOK 2304
#define CDIM 256
#define BATCH 4
#define NHEAD 8
#define HD 32
#define MDIM 128
#define MHD 16
#define HID 1024
#define HH 48
#define WW 48
#define SCALE 0.17677669529663687f

// ---------------- scratch (static __device__, no allocs) ----------------
__device__ float g_S [BATCH*NTOK*CDIM];
__device__ float g_Q [BATCH*NTOK*CDIM];
__device__ float g_KV[BATCH*NTOK*2*CDIM];
__device__ float g_XO[BATCH*NTOK*CDIM];
__device__ float g_CR[BATCH*NTOK*MDIM];
__device__ float g_S2[BATCH*NTOK*CDIM];
__device__ float g_N2[BATCH*NTOK*CDIM];
__device__ float g_Y1[BATCH*NTOK*HID];
__device__ float g_Y2[BATCH*NTOK*HID];
__device__ float g_Z [BATCH*NTOK*CDIM];
__device__ float g_MO[BATCH*NTOK*MDIM];

// ---------------- tf32 helpers ----------------
__device__ __forceinline__ unsigned f2tf32(float f) {
    unsigned r;
    asm("cvt.rna.tf32.f32 %0, %1;" : "=r"(r) : "f"(f));
    return r;
}
__device__ __forceinline__ float f2tf32f(float f) {
    return __uint_as_float(f2tf32(f));
}
__device__ __forceinline__ void mma_tf32(float* c,
    unsigned a0, unsigned a1, unsigned a2, unsigned a3,
    unsigned b0, unsigned b1) {
    asm("mma.sync.aligned.m16n8k8.row.col.f32.tf32.tf32.f32 "
        "{%0,%1,%2,%3}, {%4,%5,%6,%7}, {%8,%9}, {%0,%1,%2,%3};"
        : "+f"(c[0]), "+f"(c[1]), "+f"(c[2]), "+f"(c[3])
        : "r"(a0), "r"(a1), "r"(a2), "r"(a3), "r"(b0), "r"(b1));
}

// ---------------- tiled transpose: in (B,R,C) -> out (B,C,R) ----------------
__global__ void transpose_kernel(const float* __restrict__ in, float* __restrict__ out,
                                 int R, int C) {
    __shared__ float t[32][33];
    int b = blockIdx.z;
    int r0 = blockIdx.y * 32, c0 = blockIdx.x * 32;
    const float* ib = in + (size_t)b * R * C;
    float* ob = out + (size_t)b * R * C;
    #pragma unroll
    for (int i = threadIdx.y; i < 32; i += 8) {
        t[i][threadIdx.x] = ib[(size_t)(r0 + i) * C + c0 + threadIdx.x];
    }
    __syncthreads();
    #pragma unroll
    for (int i = threadIdx.y; i < 32; i += 8) {
        ob[(size_t)(c0 + i) * R + r0 + threadIdx.x] = t[threadIdx.x][i];
    }
}

// ---------------- LayerNorm over last dim (C=256), warp per row ----------------
__global__ void ln_rows_kernel(const float* __restrict__ in, float* __restrict__ out,
                               const float* __restrict__ g, const float* __restrict__ bb,
                               int rows) {
    int warp = (blockIdx.x * blockDim.x + threadIdx.x) >> 5;
    int lane = threadIdx.x & 31;
    if (warp >= rows) return;
    const float* row = in + (size_t)warp * CDIM;
    float* orow = out + (size_t)warp * CDIM;
    float v[8];
    float s = 0.f, s2 = 0.f;
    #pragma unroll
    for (int i = 0; i < 8; i++) {
        v[i] = row[lane + i * 32];
        s += v[i];
        s2 += v[i] * v[i];
    }
    #pragma unroll
    for (int o = 16; o; o >>= 1) {
        s  += __shfl_xor_sync(0xffffffffu, s,  o);
        s2 += __shfl_xor_sync(0xffffffffu, s2, o);
    }
    float mean = s * (1.f / CDIM);
    float var  = s2 * (1.f / CDIM) - mean * mean;
    float rstd = rsqrtf(var + 1e-5f);
    #pragma unroll
    for (int i = 0; i < 8; i++) {
        int c = lane + i * 32;
        orow[c] = (v[i] - mean) * rstd * g[c] + bb[c];
    }
}

// ---------------- tf32 tensor-core GEMM: 64x128 tile, double-buffered ----------------
// C[M,N] = op(A)[M,K] @ B[K,N] + bias[N] (+ resid[M,N])
// Smaller M-tile -> 2x grid -> 2 CTAs/SM (cross-CTA latency hiding).
__global__ __launch_bounds__(256)
void gemm_kernel(const float* __restrict__ A, const float* __restrict__ B,
                 const float* __restrict__ bias, const float* __restrict__ resid,
                 float* __restrict__ C, int M, int K, int N,
                 int swapHalf, int subCE,
                 const float* __restrict__ corw, const float* __restrict__ corb) {
    __shared__ float As[2][16][68];    // [stage][k][m] tf32 bits (64 rows + pad)
    __shared__ float Bs[2][16][132];   // [stage][k][n] tf32 bits
    int tid = threadIdx.x;
    int wid = tid >> 5, lane = tid & 31;
    int gid = lane >> 2, tig = lane & 3;
    int wm = wid & 1, wn = wid >> 1;           // warp tile: rows wm*32+.., cols wn*32+..
    int m0 = blockIdx.y * 64, n0 = blockIdx.x * 128;

    float acc[2][4][4] = {};                   // [mf][nf][c]

    // A loader: one float4 per thread (64 rows x 16 k = 1024 floats)
    int arow = tid >> 2, aq = tid & 3;
    int gm = m0 + arow;
    int gmp = gm;
    if (swapHalf) { int b = gm / NTOK; int n = gm - b * NTOK; gmp = (b ^ 2) * NTOK + n; }
    float cx = 0.f, cy = 0.f;
    if (subCE) {
        int n = gm % NTOK;
        cx = -1.f + 2.f * (float)(n % WW) * (1.f / 47.f);
        cy = -1.f + 2.f * (float)(n / WW) * (1.f / 47.f);
    }
    // B loader: two float4 chunks (16 k x 128 n = 2048 floats)
    int brow_l[2], bc_l[2];
    #pragma unroll
    for (int it = 0; it < 2; it++) {
        int idx = tid + it * 256;
        brow_l[it] = idx >> 5; bc_l[it] = idx & 31;
    }

    float aR[4]; float4 bR[2];
    int nIter = K >> 4;

    #define FETCH(k0) {                                                         \
        if (subCE) {                                                            \
            _Pragma("unroll")                                                   \
            for (int i = 0; i < 4; i++) {                                       \
                int k = (k0) + aq * 4 + i;                                      \
                float ce = cx * corw[k] + cy * corw[128 + k] + corb[k];         \
                aR[i] = A[(size_t)gmp * K + k] - ce;                            \
            }                                                                   \
        } else {                                                                \
            *(float4*)&aR[0] =                                                  \
                *(const float4*)&A[(size_t)gmp * K + (k0) + aq * 4];            \
        }                                                                       \
        _Pragma("unroll")                                                       \
        for (int it = 0; it < 2; it++)                                          \
            bR[it] = *(const float4*)&B[(size_t)((k0) + brow_l[it]) * N + n0 + bc_l[it] * 4]; \
    }
    #define STORE(s) {                                                         \
        As[s][aq * 4 + 0][arow] = f2tf32f(aR[0]);                              \
        As[s][aq * 4 + 1][arow] = f2tf32f(aR[1]);                              \
        As[s][aq * 4 + 2][arow] = f2tf32f(aR[2]);                              \
        As[s][aq * 4 + 3][arow] = f2tf32f(aR[3]);                              \
        _Pragma("unroll")                                                      \
        for (int it = 0; it < 2; it++) {                                       \
            float4 b4 = bR[it];                                                \
            b4.x = f2tf32f(b4.x); b4.y = f2tf32f(b4.y);                        \
            b4.z = f2tf32f(b4.z); b4.w = f2tf32f(b4.w);                        \
            *(float4*)&Bs[s][brow_l[it]][bc_l[it] * 4] = b4;                   \
        }                                                                      \
    }

    FETCH(0);
    STORE(0);

    for (int ki = 0; ki < nIter; ki++) {
        __syncthreads();
        if (ki + 1 < nIter) FETCH((ki + 1) << 4);
        int s = ki & 1;
        #pragma unroll
        for (int ks = 0; ks < 2; ks++) {
            int kb = ks * 8;
            unsigned af[2][4];
            #pragma unroll
            for (int mf = 0; mf < 2; mf++) {
                int mr = wm * 32 + mf * 16 + gid;
                af[mf][0] = __float_as_uint(As[s][kb + tig][mr]);
                af[mf][1] = __float_as_uint(As[s][kb + tig][mr + 8]);
                af[mf][2] = __float_as_uint(As[s][kb + tig + 4][mr]);
                af[mf][3] = __float_as_uint(As[s][kb + tig + 4][mr + 8]);
            }
            unsigned bf[4][2];
            #pragma unroll
            for (int nf = 0; nf < 4; nf++) {
                int nc = wn * 32 + nf * 8 + gid;
                bf[nf][0] = __float_as_uint(Bs[s][kb + tig][nc]);
                bf[nf][1] = __float_as_uint(Bs[s][kb + tig + 4][nc]);
            }
            #pragma unroll
            for (int mf = 0; mf < 2; mf++)
                #pragma unroll
                for (int nf = 0; nf < 4; nf++)
                    mma_tf32(acc[mf][nf], af[mf][0], af[mf][1], af[mf][2], af[mf][3],
                             bf[nf][0], bf[nf][1]);
        }
        if (ki + 1 < nIter) STORE((ki + 1) & 1);
    }
    #undef FETCH
    #undef STORE

    // epilogue
    #pragma unroll
    for (int nf = 0; nf < 4; nf++) {
        int col = n0 + wn * 32 + nf * 8 + 2 * tig;
        float2 bi = *(const float2*)&bias[col];
        #pragma unroll
        for (int mf = 0; mf < 2; mf++) {
            #pragma unroll
            for (int r = 0; r < 2; r++) {
                int m = m0 + wm * 32 + mf * 16 + gid + 8 * r;
                float2 v = make_float2(acc[mf][nf][r * 2]     + bi.x,
                                       acc[mf][nf][r * 2 + 1] + bi.y);
                if (resid) {
                    float2 rv = *(const float2*)&resid[(size_t)m * N + col];
                    v.x += rv.x; v.y += rv.y;
                }
                *(float2*)&C[(size_t)m * N + col] = v;
            }
        }
    }
}

// ---------------- fused flash attention + motion aggregation (tf32 mma) ----------
__global__ __launch_bounds__(256)
void flash_kernel(const float* __restrict__ qb, const float* __restrict__ kvb,
                  const float* __restrict__ corw, const float* __restrict__ corb,
                  float* __restrict__ xo, float* __restrict__ cro) {
    extern __shared__ float sm[];
    float (*Ks)[36] = (float(*)[36])(sm);
    float (*Wt)[56] = (float(*)[56])(sm + 2304);
    float (*Pi)[76] = (float(*)[76])(sm + 2304 + 3584);

    int tid = threadIdx.x;
    int wid = tid >> 5, lane = tid & 31;
    int gid = lane >> 2, tig = lane & 3;
    int m0 = blockIdx.x * 128;
    int h  = blockIdx.y;
    int b  = blockIdx.z;

    const float* qbase = qb + ((size_t)b * NTOK) * CDIM + h * HD;
    const float* kbase = kvb + ((size_t)b * NTOK) * (2 * CDIM) + h * HD;
    const float* vbase = kbase + CDIM;
    const float* cwh = corw + h * MHD;
    const float* cbh = corb + h * MHD;

    unsigned qa[4][4];
    {
        size_t r0 = (size_t)(m0 + wid * 16 + gid) * CDIM;
        size_t r1 = r0 + 8 * CDIM;
        #pragma unroll
        for (int ks = 0; ks < 4; ks++) {
            qa[ks][0] = f2tf32(qbase[r0 + ks * 8 + tig]);
            qa[ks][1] = f2tf32(qbase[r1 + ks * 8 + tig]);
            qa[ks][2] = f2tf32(qbase[r0 + ks * 8 + tig + 4]);
            qa[ks][3] = f2tf32(qbase[r1 + ks * 8 + tig + 4]);
        }
    }

    float m_r[2] = {-1e30f, -1e30f};
    float l_r[2] = {0.f, 0.f};
    float O[6][4] = {};

    int lkey = tid >> 2;
    int ld0  = (tid & 3) * 8;
    int lc0  = (tid & 3) * 4;

    float4 kR0, kR1, vR0, vR1;
    {
        const float* kr = &kbase[(size_t)lkey * (2 * CDIM) + ld0];
        kR0 = *(const float4*)kr; kR1 = *(const float4*)(kr + 4);
        const float* vr = &vbase[(size_t)lkey * (2 * CDIM) + ld0];
        vR0 = *(const float4*)vr; vR1 = *(const float4*)(vr + 4);
    }

    const int NT = NTOK / 64;
    for (int kt = 0; kt < NT; kt++) {
        int n0g = kt * 64;
        __syncthreads();
        {
            uint4 u0 = make_uint4(f2tf32(kR0.x), f2tf32(kR0.y), f2tf32(kR0.z), f2tf32(kR0.w));
            uint4 u1 = make_uint4(f2tf32(kR1.x), f2tf32(kR1.y), f2tf32(kR1.z), f2tf32(kR1.w));
            *(uint4*)&Ks[lkey][ld0]     = u0;
            *(uint4*)&Ks[lkey][ld0 + 4] = u1;
            uint4 x0 = make_uint4(f2tf32(vR0.x), f2tf32(vR0.y), f2tf32(vR0.z), f2tf32(vR0.w));
            uint4 x1 = make_uint4(f2tf32(vR1.x), f2tf32(vR1.y), f2tf32(vR1.z), f2tf32(vR1.w));
            *(uint4*)&Wt[lkey][ld0]     = x0;
            *(uint4*)&Wt[lkey][ld0 + 4] = x1;
            int kn = n0g + lkey;
            float xf = -1.f + 2.f * (float)(kn % WW) * (1.f / 47.f);
            float yf = -1.f + 2.f * (float)(kn / WW) * (1.f / 47.f);
            uint4 ce;
            ce.x = f2tf32(xf * cwh[lc0 + 0] + yf * cwh[128 + lc0 + 0] + cbh[lc0 + 0]);
            ce.y = f2tf32(xf * cwh[lc0 + 1] + yf * cwh[128 + lc0 + 1] + cbh[lc0 + 1]);
            ce.z = f2tf32(xf * cwh[lc0 + 2] + yf * cwh[128 + lc0 + 2] + cbh[lc0 + 2]);
            ce.w = f2tf32(xf * cwh[lc0 + 3] + yf * cwh[128 + lc0 + 3] + cbh[lc0 + 3]);
            *(uint4*)&Wt[lkey][32 + lc0] = ce;
        }
        __syncthreads();
        if (kt + 1 < NT) {
            const float* kr = &kbase[(size_t)(n0g + 64 + lkey) * (2 * CDIM) + ld0];
            kR0 = *(const float4*)kr; kR1 = *(const float4*)(kr + 4);
            const float* vr = &vbase[(size_t)(n0g + 64 + lkey) * (2 * CDIM) + ld0];
            vR0 = *(const float4*)vr; vR1 = *(const float4*)(vr + 4);
        }

        float c[8][4] = {};
        #pragma unroll
        for (int j = 0; j < 8; j++) {
            #pragma unroll
            for (int ks = 0; ks < 4; ks++) {
                unsigned b0 = __float_as_uint(Ks[j * 8 + gid][ks * 8 + tig]);
                unsigned b1 = __float_as_uint(Ks[j * 8 + gid][ks * 8 + tig + 4]);
                mma_tf32(c[j], qa[ks][0], qa[ks][1], qa[ks][2], qa[ks][3], b0, b1);
            }
        }

        #pragma unroll
        for (int r = 0; r < 2; r++) {
            float mx = -1e30f;
            #pragma unroll
            for (int j = 0; j < 8; j++)
                mx = fmaxf(mx, fmaxf(c[j][r * 2], c[j][r * 2 + 1]));
            mx = fmaxf(mx, __shfl_xor_sync(0xffffffffu, mx, 1));
            mx = fmaxf(mx, __shfl_xor_sync(0xffffffffu, mx, 2));
            mx *= SCALE;
            float nm = fmaxf(m_r[r], mx);
            float alpha = __expf(m_r[r] - nm);
            m_r[r] = nm;
            int prow = wid * 16 + gid + 8 * r;
            float sum = 0.f;
            #pragma unroll
            for (int j = 0; j < 8; j++) {
                float p0 = __expf(c[j][r * 2]     * SCALE - nm);
                float p1 = __expf(c[j][r * 2 + 1] * SCALE - nm);
                sum += p0 + p1;
                uint2 pp = make_uint2(f2tf32(p0), f2tf32(p1));
                *(uint2*)&Pi[prow][j * 8 + 2 * tig] = pp;
            }
            sum += __shfl_xor_sync(0xffffffffu, sum, 1);
            sum += __shfl_xor_sync(0xffffffffu, sum, 2);
            l_r[r] = l_r[r] * alpha + sum;
            #pragma unroll
            for (int j = 0; j < 6; j++) {
                O[j][r * 2]     *= alpha;
                O[j][r * 2 + 1] *= alpha;
            }
        }
        #pragma unroll
        for (int ks = 0; ks < 8; ks++) {
            int kk = ks * 8;
            unsigned a0 = __float_as_uint(Pi[wid * 16 + gid][kk + tig]);
            unsigned a1 = __float_as_uint(Pi[wid * 16 + gid + 8][kk + tig]);
            unsigned a2 = __float_as_uint(Pi[wid * 16 + gid][kk + tig + 4]);
            unsigned a3 = __float_as_uint(Pi[wid * 16 + gid + 8][kk + tig + 4]);
            #pragma unroll
            for (int j = 0; j < 6; j++) {
                unsigned b0 = __float_as_uint(Wt[kk + tig][j * 8 + gid]);
                unsigned b1 = __float_as_uint(Wt[kk + tig + 4][j * 8 + gid]);
                mma_tf32(O[j], a0, a1, a2, a3, b0, b1);
            }
        }
    }

    #pragma unroll
    for (int r = 0; r < 2; r++) {
        float inv = 1.f / l_r[r];
        size_t gm = (size_t)b * NTOK + m0 + wid * 16 + gid + 8 * r;
        #pragma unroll
        for (int j = 0; j < 4; j++) {
            float2 ov = make_float2(O[j][r * 2] * inv, O[j][r * 2 + 1] * inv);
            *(float2*)&xo[gm * CDIM + h * HD + j * 8 + 2 * tig] = ov;
        }
        #pragma unroll
        for (int j = 4; j < 6; j++) {
            float2 ov = make_float2(O[j][r * 2] * inv, O[j][r * 2 + 1] * inv);
            *(float2*)&cro[gm * MDIM + h * MHD + (j - 4) * 8 + 2 * tig] = ov;
        }
    }
}

// ---------------- depthwise 3x3 conv + bias + exact GELU (smem row tiling) ------
// block = (row h, 64-channel chunk, batch); 3 input rows staged in smem
__global__ __launch_bounds__(256)
void dwconv_gelu_kernel(const float* __restrict__ y, const float* __restrict__ w,
                        const float* __restrict__ bias, float* __restrict__ out) {
    __shared__ float rows[3][WW][64];
    __shared__ float wsm[64][9];
    __shared__ float bsm[64];
    int b = blockIdx.z, h = blockIdx.x, ch0 = blockIdx.y * 64;
    int tid = threadIdx.x;
    for (int i = tid; i < 64 * 9; i += 256) wsm[i / 9][i % 9] = w[(ch0 + i / 9) * 9 + i % 9];
    if (tid < 64) bsm[tid] = bias[ch0 + tid];
    const float* yb = y + (size_t)b * NTOK * HID;
    #pragma unroll
    for (int r = 0; r < 3; r++) {
        int h2 = h - 1 + r;
        if (h2 >= 0 && h2 < HH) {
            for (int idx = tid; idx < WW * 16; idx += 256) {
                int w2 = idx >> 4, c4 = (idx & 15) * 4;
                *(float4*)&rows[r][w2][c4] =
                    *(const float4*)&yb[(size_t)(h2 * WW + w2) * HID + ch0 + c4];
            }
        } else {
            for (int idx = tid; idx < WW * 16; idx += 256) {
                int w2 = idx >> 4, c4 = (idx & 15) * 4;
                *(float4*)&rows[r][w2][c4] = make_float4(0.f, 0.f, 0.f, 0.f);
            }
        }
    }
    __syncthreads();
    for (int idx = tid; idx < WW * 64; idx += 256) {
        int wc = idx >> 6, c = idx & 63;
        float acc = bsm[c];
        #pragma unroll
        for (int dh = 0; dh < 3; dh++) {
            #pragma unroll
            for (int dw = 0; dw < 3; dw++) {
                int w2 = wc + dw - 1;
                if (w2 >= 0 && w2 < WW)
                    acc += rows[dh][w2][c] * wsm[c][dh * 3 + dw];
            }
        }
        float gv = 0.5f * acc * (1.f + erff(acc * 0.70710678118654752f));
        out[((size_t)b * NTOK + h * WW + wc) * HID + ch0 + c] = gv;
    }
}

// ---------------- launch ----------------
extern "C" void kernel_launch(void* const* d_in, const int* in_sizes, int n_in,
                              void* d_out, int out_size) {
    const float* feat0   = (const float*)d_in[0];
    const float* feat1   = (const float*)d_in[1];
    const float* norm1_g = (const float*)d_in[2];
    const float* norm1_b = (const float*)d_in[3];
    const float* norm2_g = (const float*)d_in[4];
    const float* norm2_b = (const float*)d_in[5];
    const float* q_w     = (const float*)d_in[6];
    const float* q_b     = (const float*)d_in[7];
    const float* kv_w    = (const float*)d_in[8];
    const float* kv_b    = (const float*)d_in[9];
    const float* cor_w   = (const float*)d_in[10];
    const float* cor_b   = (const float*)d_in[11];
    const float* mot_w   = (const float*)d_in[12];
    const float* mot_b   = (const float*)d_in[13];
    const float* proj_w  = (const float*)d_in[14];
    const float* proj_b  = (const float*)d_in[15];
    const float* fc1_w   = (const float*)d_in[16];
    const float* fc1_b   = (const float*)d_in[17];
    const float* dw_w    = (const float*)d_in[18];
    const float* dw_b    = (const float*)d_in[19];
    const float* fc2_w   = (const float*)d_in[20];
    const float* fc2_b   = (const float*)d_in[21];

    float* out_main   = (float*)d_out;
    float* out_motion = out_main + (size_t)BATCH * CDIM * NTOK;

    float *pS, *pQ, *pKV, *pXO, *pCR, *pS2, *pN2, *pY1, *pY2, *pZ, *pMO;
    cudaGetSymbolAddress((void**)&pS,  g_S);
    cudaGetSymbolAddress((void**)&pQ,  g_Q);
    cudaGetSymbolAddress((void**)&pKV, g_KV);
    cudaGetSymbolAddress((void**)&pXO, g_XO);
    cudaGetSymbolAddress((void**)&pCR, g_CR);
    cudaGetSymbolAddress((void**)&pS2, g_S2);
    cudaGetSymbolAddress((void**)&pN2, g_N2);
    cudaGetSymbolAddress((void**)&pY1, g_Y1);
    cudaGetSymbolAddress((void**)&pY2, g_Y2);
    cudaGetSymbolAddress((void**)&pZ,  g_Z);
    cudaGetSymbolAddress((void**)&pMO, g_MO);

    dim3 tb(32, 8);

    transpose_kernel<<<dim3(NTOK / 32, CDIM / 32, 2), tb>>>(feat0, pS, CDIM, NTOK);
    transpose_kernel<<<dim3(NTOK / 32, CDIM / 32, 2), tb>>>(feat1, pS + 2 * (size_t)NTOK * CDIM, CDIM, NTOK);
    ln_rows_kernel<<<(BATCH * NTOK) / 8, 256>>>(pS, pS, norm1_g, norm1_b, BATCH * NTOK);

    int M = BATCH * NTOK;
    gemm_kernel<<<dim3(CDIM / 128, M / 64), 256>>>(pS, q_w, q_b, nullptr, pQ,
                                                   M, CDIM, CDIM, 0, 0, nullptr, nullptr);
    gemm_kernel<<<dim3(2 * CDIM / 128, M / 64), 256>>>(pS, kv_w, kv_b, nullptr, pKV,
                                                       M, CDIM, 2 * CDIM, 1, 0, nullptr, nullptr);
    size_t fsmem = (2304 + 3584 + 128 * 76) * sizeof(float);   // 62464 B
    cudaFuncSetAttribute(flash_kernel, cudaFuncAttributeMaxDynamicSharedMemorySize, (int)fsmem);
    flash_kernel<<<dim3(NTOK / 128, NHEAD, BATCH), 256, fsmem>>>(pQ, pKV, cor_w, cor_b, pXO, pCR);
    gemm_kernel<<<dim3(CDIM / 128, M / 64), 256>>>(pXO, proj_w, proj_b, pS, pS2,
                                                   M, CDIM, CDIM, 0, 0, nullptr, nullptr);
    ln_rows_kernel<<<(BATCH * NTOK) / 8, 256>>>(pS2, pN2, norm2_g, norm2_b, BATCH * NTOK);
    gemm_kernel<<<dim3(HID / 128, M / 64), 256>>>(pN2, fc1_w, fc1_b, nullptr, pY1,
                                                  M, CDIM, HID, 0, 0, nullptr, nullptr);
    dwconv_gelu_kernel<<<dim3(HH, HID / 64, BATCH), 256>>>(pY1, dw_w, dw_b, pY2);
    gemm_kernel<<<dim3(CDIM / 128, M / 64), 256>>>(pY2, fc2_w, fc2_b, pS2, pZ,
                                                   M, HID, CDIM, 0, 0, nullptr, nullptr);
    gemm_kernel<<<dim3(MDIM / 128, M / 64), 256>>>(pCR, mot_w, mot_b, nullptr, pMO,
                                                   M, MDIM, MDIM, 0, 1, cor_w, cor_b);
    transpose_kernel<<<dim3(CDIM / 32, NTOK / 32, BATCH), tb>>>(pZ, out_main, NTOK, CDIM);
    transpose_kernel<<<dim3(MDIM / 32, NTOK / 32, BATCH), tb>>>(pMO, out_motion, NTOK, MDIM);
}

// round 9
// speedup vs baseline: 1.0682x; 1.0682x over previous
#include <cuda_runtime.h>
#include <math.h>

#define NTOK 2304
#define CDIM 256
#define BATCH 4
#define NHEAD 8
#define HD 32
#define MDIM 128
#define MHD 16
#define HID 1024
#define HH 48
#define WW 48
#define SCALE 0.17677669529663687f

// ---------------- scratch (static __device__, no allocs) ----------------
__device__ float g_S [BATCH*NTOK*CDIM];
__device__ float g_Q [BATCH*NTOK*CDIM];
__device__ float g_KV[BATCH*NTOK*2*CDIM];
__device__ float g_XO[BATCH*NTOK*CDIM];
__device__ float g_CR[BATCH*NTOK*MDIM];
__device__ float g_S2[BATCH*NTOK*CDIM];
__device__ float g_N2[BATCH*NTOK*CDIM];
__device__ float g_Y1[BATCH*NTOK*HID];
__device__ float g_Y2[BATCH*NTOK*HID];
__device__ float g_Z [BATCH*NTOK*CDIM];
__device__ float g_MO[BATCH*NTOK*MDIM];

// ---------------- tf32 helpers ----------------
__device__ __forceinline__ unsigned f2tf32(float f) {
    unsigned r;
    asm("cvt.rna.tf32.f32 %0, %1;" : "=r"(r) : "f"(f));
    return r;
}
__device__ __forceinline__ float f2tf32f(float f) {
    return __uint_as_float(f2tf32(f));
}
__device__ __forceinline__ void mma_tf32(float* c,
    unsigned a0, unsigned a1, unsigned a2, unsigned a3,
    unsigned b0, unsigned b1) {
    asm("mma.sync.aligned.m16n8k8.row.col.f32.tf32.tf32.f32 "
        "{%0,%1,%2,%3}, {%4,%5,%6,%7}, {%8,%9}, {%0,%1,%2,%3};"
        : "+f"(c[0]), "+f"(c[1]), "+f"(c[2]), "+f"(c[3])
        : "r"(a0), "r"(a1), "r"(a2), "r"(a3), "r"(b0), "r"(b1));
}

// ---------------- tiled transpose: in (B,R,C) -> out (B,C,R) ----------------
__global__ void transpose_kernel(const float* __restrict__ in, float* __restrict__ out,
                                 int R, int C) {
    __shared__ float t[32][33];
    int b = blockIdx.z;
    int r0 = blockIdx.y * 32, c0 = blockIdx.x * 32;
    const float* ib = in + (size_t)b * R * C;
    float* ob = out + (size_t)b * R * C;
    #pragma unroll
    for (int i = threadIdx.y; i < 32; i += 8) {
        t[i][threadIdx.x] = ib[(size_t)(r0 + i) * C + c0 + threadIdx.x];
    }
    __syncthreads();
    #pragma unroll
    for (int i = threadIdx.y; i < 32; i += 8) {
        ob[(size_t)(c0 + i) * R + r0 + threadIdx.x] = t[threadIdx.x][i];
    }
}

// ---------------- LayerNorm over last dim (C=256), warp per row ----------------
__global__ void ln_rows_kernel(const float* __restrict__ in, float* __restrict__ out,
                               const float* __restrict__ g, const float* __restrict__ bb,
                               int rows) {
    int warp = (blockIdx.x * blockDim.x + threadIdx.x) >> 5;
    int lane = threadIdx.x & 31;
    if (warp >= rows) return;
    const float* row = in + (size_t)warp * CDIM;
    float* orow = out + (size_t)warp * CDIM;
    float v[8];
    float s = 0.f, s2 = 0.f;
    #pragma unroll
    for (int i = 0; i < 8; i++) {
        v[i] = row[lane + i * 32];
        s += v[i];
        s2 += v[i] * v[i];
    }
    #pragma unroll
    for (int o = 16; o; o >>= 1) {
        s  += __shfl_xor_sync(0xffffffffu, s,  o);
        s2 += __shfl_xor_sync(0xffffffffu, s2, o);
    }
    float mean = s * (1.f / CDIM);
    float var  = s2 * (1.f / CDIM) - mean * mean;
    float rstd = rsqrtf(var + 1e-5f);
    #pragma unroll
    for (int i = 0; i < 8; i++) {
        int c = lane + i * 32;
        orow[c] = (v[i] - mean) * rstd * g[c] + bb[c];
    }
}

// ---------------- tf32 tensor-core GEMM: 128x128 tile, BK=32, double-buffered ----
// C[M,N] = op(A)[M,K] @ B[K,N] + bias[N] (+ resid[M,N])
// BK=32 halves barrier count vs BK=16; 64 MMAs/warp between syncs.
__global__ __launch_bounds__(256)
void gemm_kernel(const float* __restrict__ A, const float* __restrict__ B,
                 const float* __restrict__ bias, const float* __restrict__ resid,
                 float* __restrict__ C, int M, int K, int N,
                 int swapHalf, int subCE,
                 const float* __restrict__ corw, const float* __restrict__ corb) {
    extern __shared__ float dsm[];
    float (*As)[32][132] = (float(*)[32][132])dsm;          // [2][32][132]
    float (*Bs)[32][132] = (float(*)[32][132])(dsm + 8448); // [2][32][132]
    int tid = threadIdx.x;
    int wid = tid >> 5, lane = tid & 31;
    int gid = lane >> 2, tig = lane & 3;
    int wm = wid & 1, wn = wid >> 1;
    int m0 = blockIdx.y * 128, n0 = blockIdx.x * 128;

    float acc[4][4][4] = {};

    // loader geometry: 4 chunks each for A and B
    // A: 128 rows x 8 k-quads; B: 32 k-rows x 32 n-quads
    int gmp_l[4]; float cx_l[4], cy_l[4]; int arow_l[4], aq_l[4];
    int brow_l[4], bc_l[4];
    #pragma unroll
    for (int it = 0; it < 4; it++) {
        int idx = tid + it * 256;
        int arow = idx >> 3, aq = idx & 7;
        arow_l[it] = arow; aq_l[it] = aq;
        int gm = m0 + arow;
        int gmp = gm;
        if (swapHalf) { int b = gm / NTOK; int n = gm - b * NTOK; gmp = (b ^ 2) * NTOK + n; }
        gmp_l[it] = gmp;
        cx_l[it] = 0.f; cy_l[it] = 0.f;
        if (subCE) {
            int n = gm % NTOK;
            cx_l[it] = -1.f + 2.f * (float)(n % WW) * (1.f / 47.f);
            cy_l[it] = -1.f + 2.f * (float)(n / WW) * (1.f / 47.f);
        }
        brow_l[it] = idx >> 5; bc_l[it] = idx & 31;
    }

    float aR[4][4]; float4 bR[4];
    int nIter = K >> 5;

    #define FETCH(k0) {                                                         \
        _Pragma("unroll")                                                       \
        for (int it = 0; it < 4; it++) {                                        \
            if (subCE) {                                                        \
                _Pragma("unroll")                                               \
                for (int i = 0; i < 4; i++) {                                   \
                    int k = (k0) + aq_l[it] * 4 + i;                            \
                    float ce = cx_l[it] * corw[k] + cy_l[it] * corw[128 + k] + corb[k]; \
                    aR[it][i] = A[(size_t)gmp_l[it] * K + k] - ce;              \
                }                                                               \
            } else {                                                            \
                *(float4*)&aR[it][0] =                                          \
                    *(const float4*)&A[(size_t)gmp_l[it] * K + (k0) + aq_l[it] * 4]; \
            }                                                                   \
            bR[it] = *(const float4*)&B[(size_t)((k0) + brow_l[it]) * N + n0 + bc_l[it] * 4]; \
        }                                                                       \
    }
    #define STORE(s) {                                                         \
        _Pragma("unroll")                                                      \
        for (int it = 0; it < 4; it++) {                                       \
            As[s][aq_l[it] * 4 + 0][arow_l[it]] = f2tf32f(aR[it][0]);          \
            As[s][aq_l[it] * 4 + 1][arow_l[it]] = f2tf32f(aR[it][1]);          \
            As[s][aq_l[it] * 4 + 2][arow_l[it]] = f2tf32f(aR[it][2]);          \
            As[s][aq_l[it] * 4 + 3][arow_l[it]] = f2tf32f(aR[it][3]);          \
            float4 b4 = bR[it];                                                \
            b4.x = f2tf32f(b4.x); b4.y = f2tf32f(b4.y);                        \
            b4.z = f2tf32f(b4.z); b4.w = f2tf32f(b4.w);                        \
            *(float4*)&Bs[s][brow_l[it]][bc_l[it] * 4] = b4;                   \
        }                                                                      \
    }

    FETCH(0);
    STORE(0);

    for (int ki = 0; ki < nIter; ki++) {
        __syncthreads();
        if (ki + 1 < nIter) FETCH((ki + 1) << 5);
        int s = ki & 1;
        #pragma unroll
        for (int ks = 0; ks < 4; ks++) {
            int kb = ks * 8;
            unsigned af[4][4];
            #pragma unroll
            for (int mf = 0; mf < 4; mf++) {
                int mr = wm * 64 + mf * 16 + gid;
                af[mf][0] = __float_as_uint(As[s][kb + tig][mr]);
                af[mf][1] = __float_as_uint(As[s][kb + tig][mr + 8]);
                af[mf][2] = __float_as_uint(As[s][kb + tig + 4][mr]);
                af[mf][3] = __float_as_uint(As[s][kb + tig + 4][mr + 8]);
            }
            unsigned bf[4][2];
            #pragma unroll
            for (int nf = 0; nf < 4; nf++) {
                int nc = wn * 32 + nf * 8 + gid;
                bf[nf][0] = __float_as_uint(Bs[s][kb + tig][nc]);
                bf[nf][1] = __float_as_uint(Bs[s][kb + tig + 4][nc]);
            }
            #pragma unroll
            for (int mf = 0; mf < 4; mf++)
                #pragma unroll
                for (int nf = 0; nf < 4; nf++)
                    mma_tf32(acc[mf][nf], af[mf][0], af[mf][1], af[mf][2], af[mf][3],
                             bf[nf][0], bf[nf][1]);
        }
        if (ki + 1 < nIter) STORE((ki + 1) & 1);
    }
    #undef FETCH
    #undef STORE

    // epilogue
    #pragma unroll
    for (int nf = 0; nf < 4; nf++) {
        int col = n0 + wn * 32 + nf * 8 + 2 * tig;
        float2 bi = *(const float2*)&bias[col];
        #pragma unroll
        for (int mf = 0; mf < 4; mf++) {
            #pragma unroll
            for (int r = 0; r < 2; r++) {
                int m = m0 + wm * 64 + mf * 16 + gid + 8 * r;
                float2 v = make_float2(acc[mf][nf][r * 2]     + bi.x,
                                       acc[mf][nf][r * 2 + 1] + bi.y);
                if (resid) {
                    float2 rv = *(const float2*)&resid[(size_t)m * N + col];
                    v.x += rv.x; v.y += rv.y;
                }
                *(float2*)&C[(size_t)m * N + col] = v;
            }
        }
    }
}

// ---------------- fused flash attention + motion aggregation (tf32 mma) ----------
__global__ __launch_bounds__(256)
void flash_kernel(const float* __restrict__ qb, const float* __restrict__ kvb,
                  const float* __restrict__ corw, const float* __restrict__ corb,
                  float* __restrict__ xo, float* __restrict__ cro) {
    extern __shared__ float sm[];
    float (*Ks)[36] = (float(*)[36])(sm);
    float (*Wt)[56] = (float(*)[56])(sm + 2304);
    float (*Pi)[76] = (float(*)[76])(sm + 2304 + 3584);

    int tid = threadIdx.x;
    int wid = tid >> 5, lane = tid & 31;
    int gid = lane >> 2, tig = lane & 3;
    int m0 = blockIdx.x * 128;
    int h  = blockIdx.y;
    int b  = blockIdx.z;

    const float* qbase = qb + ((size_t)b * NTOK) * CDIM + h * HD;
    const float* kbase = kvb + ((size_t)b * NTOK) * (2 * CDIM) + h * HD;
    const float* vbase = kbase + CDIM;
    const float* cwh = corw + h * MHD;
    const float* cbh = corb + h * MHD;

    unsigned qa[4][4];
    {
        size_t r0 = (size_t)(m0 + wid * 16 + gid) * CDIM;
        size_t r1 = r0 + 8 * CDIM;
        #pragma unroll
        for (int ks = 0; ks < 4; ks++) {
            qa[ks][0] = f2tf32(qbase[r0 + ks * 8 + tig]);
            qa[ks][1] = f2tf32(qbase[r1 + ks * 8 + tig]);
            qa[ks][2] = f2tf32(qbase[r0 + ks * 8 + tig + 4]);
            qa[ks][3] = f2tf32(qbase[r1 + ks * 8 + tig + 4]);
        }
    }

    float m_r[2] = {-1e30f, -1e30f};
    float l_r[2] = {0.f, 0.f};
    float O[6][4] = {};

    int lkey = tid >> 2;
    int ld0  = (tid & 3) * 8;
    int lc0  = (tid & 3) * 4;

    float4 kR0, kR1, vR0, vR1;
    {
        const float* kr = &kbase[(size_t)lkey * (2 * CDIM) + ld0];
        kR0 = *(const float4*)kr; kR1 = *(const float4*)(kr + 4);
        const float* vr = &vbase[(size_t)lkey * (2 * CDIM) + ld0];
        vR0 = *(const float4*)vr; vR1 = *(const float4*)(vr + 4);
    }

    const int NT = NTOK / 64;
    for (int kt = 0; kt < NT; kt++) {
        int n0g = kt * 64;
        __syncthreads();
        {
            uint4 u0 = make_uint4(f2tf32(kR0.x), f2tf32(kR0.y), f2tf32(kR0.z), f2tf32(kR0.w));
            uint4 u1 = make_uint4(f2tf32(kR1.x), f2tf32(kR1.y), f2tf32(kR1.z), f2tf32(kR1.w));
            *(uint4*)&Ks[lkey][ld0]     = u0;
            *(uint4*)&Ks[lkey][ld0 + 4] = u1;
            uint4 x0 = make_uint4(f2tf32(vR0.x), f2tf32(vR0.y), f2tf32(vR0.z), f2tf32(vR0.w));
            uint4 x1 = make_uint4(f2tf32(vR1.x), f2tf32(vR1.y), f2tf32(vR1.z), f2tf32(vR1.w));
            *(uint4*)&Wt[lkey][ld0]     = x0;
            *(uint4*)&Wt[lkey][ld0 + 4] = x1;
            int kn = n0g + lkey;
            float xf = -1.f + 2.f * (float)(kn % WW) * (1.f / 47.f);
            float yf = -1.f + 2.f * (float)(kn / WW) * (1.f / 47.f);
            uint4 ce;
            ce.x = f2tf32(xf * cwh[lc0 + 0] + yf * cwh[128 + lc0 + 0] + cbh[lc0 + 0]);
            ce.y = f2tf32(xf * cwh[lc0 + 1] + yf * cwh[128 + lc0 + 1] + cbh[lc0 + 1]);
            ce.z = f2tf32(xf * cwh[lc0 + 2] + yf * cwh[128 + lc0 + 2] + cbh[lc0 + 2]);
            ce.w = f2tf32(xf * cwh[lc0 + 3] + yf * cwh[128 + lc0 + 3] + cbh[lc0 + 3]);
            *(uint4*)&Wt[lkey][32 + lc0] = ce;
        }
        __syncthreads();
        if (kt + 1 < NT) {
            const float* kr = &kbase[(size_t)(n0g + 64 + lkey) * (2 * CDIM) + ld0];
            kR0 = *(const float4*)kr; kR1 = *(const float4*)(kr + 4);
            const float* vr = &vbase[(size_t)(n0g + 64 + lkey) * (2 * CDIM) + ld0];
            vR0 = *(const float4*)vr; vR1 = *(const float4*)(vr + 4);
        }

        float c[8][4] = {};
        #pragma unroll
        for (int j = 0; j < 8; j++) {
            #pragma unroll
            for (int ks = 0; ks < 4; ks++) {
                unsigned b0 = __float_as_uint(Ks[j * 8 + gid][ks * 8 + tig]);
                unsigned b1 = __float_as_uint(Ks[j * 8 + gid][ks * 8 + tig + 4]);
                mma_tf32(c[j], qa[ks][0], qa[ks][1], qa[ks][2], qa[ks][3], b0, b1);
            }
        }

        #pragma unroll
        for (int r = 0; r < 2; r++) {
            float mx = -1e30f;
            #pragma unroll
            for (int j = 0; j < 8; j++)
                mx = fmaxf(mx, fmaxf(c[j][r * 2], c[j][r * 2 + 1]));
            mx = fmaxf(mx, __shfl_xor_sync(0xffffffffu, mx, 1));
            mx = fmaxf(mx, __shfl_xor_sync(0xffffffffu, mx, 2));
            mx *= SCALE;
            float nm = fmaxf(m_r[r], mx);
            float alpha = __expf(m_r[r] - nm);
            m_r[r] = nm;
            int prow = wid * 16 + gid + 8 * r;
            float sum = 0.f;
            #pragma unroll
            for (int j = 0; j < 8; j++) {
                float p0 = __expf(c[j][r * 2]     * SCALE - nm);
                float p1 = __expf(c[j][r * 2 + 1] * SCALE - nm);
                sum += p0 + p1;
                uint2 pp = make_uint2(f2tf32(p0), f2tf32(p1));
                *(uint2*)&Pi[prow][j * 8 + 2 * tig] = pp;
            }
            sum += __shfl_xor_sync(0xffffffffu, sum, 1);
            sum += __shfl_xor_sync(0xffffffffu, sum, 2);
            l_r[r] = l_r[r] * alpha + sum;
            #pragma unroll
            for (int j = 0; j < 6; j++) {
                O[j][r * 2]     *= alpha;
                O[j][r * 2 + 1] *= alpha;
            }
        }
        #pragma unroll
        for (int ks = 0; ks < 8; ks++) {
            int kk = ks * 8;
            unsigned a0 = __float_as_uint(Pi[wid * 16 + gid][kk + tig]);
            unsigned a1 = __float_as_uint(Pi[wid * 16 + gid + 8][kk + tig]);
            unsigned a2 = __float_as_uint(Pi[wid * 16 + gid][kk + tig + 4]);
            unsigned a3 = __float_as_uint(Pi[wid * 16 + gid + 8][kk + tig + 4]);
            #pragma unroll
            for (int j = 0; j < 6; j++) {
                unsigned b0 = __float_as_uint(Wt[kk + tig][j * 8 + gid]);
                unsigned b1 = __float_as_uint(Wt[kk + tig + 4][j * 8 + gid]);
                mma_tf32(O[j], a0, a1, a2, a3, b0, b1);
            }
        }
    }

    #pragma unroll
    for (int r = 0; r < 2; r++) {
        float inv = 1.f / l_r[r];
        size_t gm = (size_t)b * NTOK + m0 + wid * 16 + gid + 8 * r;
        #pragma unroll
        for (int j = 0; j < 4; j++) {
            float2 ov = make_float2(O[j][r * 2] * inv, O[j][r * 2 + 1] * inv);
            *(float2*)&xo[gm * CDIM + h * HD + j * 8 + 2 * tig] = ov;
        }
        #pragma unroll
        for (int j = 4; j < 6; j++) {
            float2 ov = make_float2(O[j][r * 2] * inv, O[j][r * 2 + 1] * inv);
            *(float2*)&cro[gm * MDIM + h * MHD + (j - 4) * 8 + 2 * tig] = ov;
        }
    }
}

// ---------------- depthwise 3x3 conv + bias + exact GELU (smem row tiling) ------
__global__ __launch_bounds__(256)
void dwconv_gelu_kernel(const float* __restrict__ y, const float* __restrict__ w,
                        const float* __restrict__ bias, float* __restrict__ out) {
    __shared__ float rows[3][WW][64];
    __shared__ float wsm[64][9];
    __shared__ float bsm[64];
    int b = blockIdx.z, h = blockIdx.x, ch0 = blockIdx.y * 64;
    int tid = threadIdx.x;
    for (int i = tid; i < 64 * 9; i += 256) wsm[i / 9][i % 9] = w[(ch0 + i / 9) * 9 + i % 9];
    if (tid < 64) bsm[tid] = bias[ch0 + tid];
    const float* yb = y + (size_t)b * NTOK * HID;
    #pragma unroll
    for (int r = 0; r < 3; r++) {
        int h2 = h - 1 + r;
        if (h2 >= 0 && h2 < HH) {
            for (int idx = tid; idx < WW * 16; idx += 256) {
                int w2 = idx >> 4, c4 = (idx & 15) * 4;
                *(float4*)&rows[r][w2][c4] =
                    *(const float4*)&yb[(size_t)(h2 * WW + w2) * HID + ch0 + c4];
            }
        } else {
            for (int idx = tid; idx < WW * 16; idx += 256) {
                int w2 = idx >> 4, c4 = (idx & 15) * 4;
                *(float4*)&rows[r][w2][c4] = make_float4(0.f, 0.f, 0.f, 0.f);
            }
        }
    }
    __syncthreads();
    for (int idx = tid; idx < WW * 64; idx += 256) {
        int wc = idx >> 6, c = idx & 63;
        float acc = bsm[c];
        #pragma unroll
        for (int dh = 0; dh < 3; dh++) {
            #pragma unroll
            for (int dw = 0; dw < 3; dw++) {
                int w2 = wc + dw - 1;
                if (w2 >= 0 && w2 < WW)
                    acc += rows[dh][w2][c] * wsm[c][dh * 3 + dw];
            }
        }
        float gv = 0.5f * acc * (1.f + erff(acc * 0.70710678118654752f));
        out[((size_t)b * NTOK + h * WW + wc) * HID + ch0 + c] = gv;
    }
}

// ---------------- launch ----------------
extern "C" void kernel_launch(void* const* d_in, const int* in_sizes, int n_in,
                              void* d_out, int out_size) {
    const float* feat0   = (const float*)d_in[0];
    const float* feat1   = (const float*)d_in[1];
    const float* norm1_g = (const float*)d_in[2];
    const float* norm1_b = (const float*)d_in[3];
    const float* norm2_g = (const float*)d_in[4];
    const float* norm2_b = (const float*)d_in[5];
    const float* q_w     = (const float*)d_in[6];
    const float* q_b     = (const float*)d_in[7];
    const float* kv_w    = (const float*)d_in[8];
    const float* kv_b    = (const float*)d_in[9];
    const float* cor_w   = (const float*)d_in[10];
    const float* cor_b   = (const float*)d_in[11];
    const float* mot_w   = (const float*)d_in[12];
    const float* mot_b   = (const float*)d_in[13];
    const float* proj_w  = (const float*)d_in[14];
    const float* proj_b  = (const float*)d_in[15];
    const float* fc1_w   = (const float*)d_in[16];
    const float* fc1_b   = (const float*)d_in[17];
    const float* dw_w    = (const float*)d_in[18];
    const float* dw_b    = (const float*)d_in[19];
    const float* fc2_w   = (const float*)d_in[20];
    const float* fc2_b   = (const float*)d_in[21];

    float* out_main   = (float*)d_out;
    float* out_motion = out_main + (size_t)BATCH * CDIM * NTOK;

    float *pS, *pQ, *pKV, *pXO, *pCR, *pS2, *pN2, *pY1, *pY2, *pZ, *pMO;
    cudaGetSymbolAddress((void**)&pS,  g_S);
    cudaGetSymbolAddress((void**)&pQ,  g_Q);
    cudaGetSymbolAddress((void**)&pKV, g_KV);
    cudaGetSymbolAddress((void**)&pXO, g_XO);
    cudaGetSymbolAddress((void**)&pCR, g_CR);
    cudaGetSymbolAddress((void**)&pS2, g_S2);
    cudaGetSymbolAddress((void**)&pN2, g_N2);
    cudaGetSymbolAddress((void**)&pY1, g_Y1);
    cudaGetSymbolAddress((void**)&pY2, g_Y2);
    cudaGetSymbolAddress((void**)&pZ,  g_Z);
    cudaGetSymbolAddress((void**)&pMO, g_MO);

    dim3 tb(32, 8);

    transpose_kernel<<<dim3(NTOK / 32, CDIM / 32, 2), tb>>>(feat0, pS, CDIM, NTOK);
    transpose_kernel<<<dim3(NTOK / 32, CDIM / 32, 2), tb>>>(feat1, pS + 2 * (size_t)NTOK * CDIM, CDIM, NTOK);
    ln_rows_kernel<<<(BATCH * NTOK) / 8, 256>>>(pS, pS, norm1_g, norm1_b, BATCH * NTOK);

    int M = BATCH * NTOK;
    size_t gsmem = 16896 * sizeof(float);   // 67584 B (2-stage BK=32)
    cudaFuncSetAttribute(gemm_kernel, cudaFuncAttributeMaxDynamicSharedMemorySize, (int)gsmem);

    gemm_kernel<<<dim3(CDIM / 128, M / 128), 256, gsmem>>>(pS, q_w, q_b, nullptr, pQ,
                                                           M, CDIM, CDIM, 0, 0, nullptr, nullptr);
    gemm_kernel<<<dim3(2 * CDIM / 128, M / 128), 256, gsmem>>>(pS, kv_w, kv_b, nullptr, pKV,
                                                               M, CDIM, 2 * CDIM, 1, 0, nullptr, nullptr);
    size_t fsmem = (2304 + 3584 + 128 * 76) * sizeof(float);   // 62464 B
    cudaFuncSetAttribute(flash_kernel, cudaFuncAttributeMaxDynamicSharedMemorySize, (int)fsmem);
    flash_kernel<<<dim3(NTOK / 128, NHEAD, BATCH), 256, fsmem>>>(pQ, pKV, cor_w, cor_b, pXO, pCR);
    gemm_kernel<<<dim3(CDIM / 128, M / 128), 256, gsmem>>>(pXO, proj_w, proj_b, pS, pS2,
                                                           M, CDIM, CDIM, 0, 0, nullptr, nullptr);
    ln_rows_kernel<<<(BATCH * NTOK) / 8, 256>>>(pS2, pN2, norm2_g, norm2_b, BATCH * NTOK);
    gemm_kernel<<<dim3(HID / 128, M / 128), 256, gsmem>>>(pN2, fc1_w, fc1_b, nullptr, pY1,
                                                          M, CDIM, HID, 0, 0, nullptr, nullptr);
    dwconv_gelu_kernel<<<dim3(HH, HID / 64, BATCH), 256>>>(pY1, dw_w, dw_b, pY2);
    gemm_kernel<<<dim3(CDIM / 128, M / 128), 256, gsmem>>>(pY2, fc2_w, fc2_b, pS2, pZ,
                                                           M, HID, CDIM, 0, 0, nullptr, nullptr);
    gemm_kernel<<<dim3(MDIM / 128, M / 128), 256, gsmem>>>(pCR, mot_w, mot_b, nullptr, pMO,
                                                           M, MDIM, MDIM, 0, 1, cor_w, cor_b);
    transpose_kernel<<<dim3(CDIM / 32, NTOK / 32, BATCH), tb>>>(pZ, out_main, NTOK, CDIM);
    transpose_kernel<<<dim3(MDIM / 32, NTOK / 32, BATCH), tb>>>(pMO, out_motion, NTOK, MDIM);
}

// round 11
// speedup vs baseline: 1.2593x; 1.1789x over previous
#include <cuda_runtime.h>
#include <math.h>

#define NTOK 2304
#define CDIM 256
#define BATCH 4
#define NHEAD 8
#define HD 32
#define MDIM 128
#define MHD 16
#define HID 1024
#define HH 48
#define WW 48
#define SCALE 0.17677669529663687f

// ---------------- scratch (static __device__, no allocs) ----------------
__device__ float g_S [BATCH*NTOK*CDIM];
__device__ float g_Q [BATCH*NTOK*CDIM];
__device__ float g_KV[BATCH*NTOK*2*CDIM];
__device__ float g_XO[BATCH*NTOK*CDIM];
__device__ float g_CR[BATCH*NTOK*MDIM];
__device__ float g_S2[BATCH*NTOK*CDIM];
__device__ float g_N2[BATCH*NTOK*CDIM];
__device__ float g_Y1[BATCH*NTOK*HID];
__device__ float g_Y2[BATCH*NTOK*HID];
__device__ float g_Z [BATCH*NTOK*CDIM];
__device__ float g_MO[BATCH*NTOK*MDIM];
// tf32-rounded weight copies
__device__ float g_WQ [CDIM*CDIM];
__device__ float g_WKV[CDIM*2*CDIM];
__device__ float g_WP [CDIM*CDIM];
__device__ float g_W1 [CDIM*HID];
__device__ float g_W2 [HID*CDIM];
__device__ float g_WM [MDIM*MDIM];
__device__ float g_RK2[3*MDIM];     // wu | wv | wb

// ---------------- tf32 helpers ----------------
__device__ __forceinline__ unsigned f2tf32(float f) {
    unsigned r;
    asm("cvt.rna.tf32.f32 %0, %1;" : "=r"(r) : "f"(f));
    return r;
}
__device__ __forceinline__ float f2tf32f(float f) {
    return __uint_as_float(f2tf32(f));
}
__device__ __forceinline__ void mma_tf32(float* c,
    unsigned a0, unsigned a1, unsigned a2, unsigned a3,
    unsigned b0, unsigned b1) {
    asm("mma.sync.aligned.m16n8k8.row.col.f32.tf32.tf32.f32 "
        "{%0,%1,%2,%3}, {%4,%5,%6,%7}, {%8,%9}, {%0,%1,%2,%3};"
        : "+f"(c[0]), "+f"(c[1]), "+f"(c[2]), "+f"(c[3])
        : "r"(a0), "r"(a1), "r"(a2), "r"(a3), "r"(b0), "r"(b1));
}

// ---------------- weight rounding prepass (tf32 rna) ----------------
__global__ void round_weights_kernel(const float4* __restrict__ wq, const float4* __restrict__ wkv,
                                     const float4* __restrict__ wp, const float4* __restrict__ w1,
                                     const float4* __restrict__ w2, const float4* __restrict__ wm,
                                     float4* oq, float4* okv, float4* op,
                                     float4* o1, float4* o2, float4* om) {
    int i = blockIdx.x * 256 + threadIdx.x;
    const float4* s; float4* d; int off;
    if      (i <  16384) { s = wq;  d = oq;  off = i; }
    else if (i <  49152) { s = wkv; d = okv; off = i - 16384; }
    else if (i <  65536) { s = wp;  d = op;  off = i - 49152; }
    else if (i < 131072) { s = w1;  d = o1;  off = i - 65536; }
    else if (i < 196608) { s = w2;  d = o2;  off = i - 131072; }
    else if (i < 200704) { s = wm;  d = om;  off = i - 196608; }
    else return;
    float4 v = s[off];
    v.x = f2tf32f(v.x); v.y = f2tf32f(v.y); v.z = f2tf32f(v.z); v.w = f2tf32f(v.w);
    d[off] = v;
}

// ---------------- rank-2 motion correction: wu=cw0@W, wv=cw1@W, wb=cb@W ------
__global__ void rk2_kernel(const float* __restrict__ cor_w, const float* __restrict__ cor_b,
                           const float* __restrict__ mot_w, float* __restrict__ rk2) {
    int i = threadIdx.x;   // 128 threads
    float su = 0.f, sv = 0.f, sb = 0.f;
    for (int k = 0; k < MDIM; k++) {
        float m = mot_w[k * MDIM + i];
        su += cor_w[k] * m;
        sv += cor_w[MDIM + k] * m;
        sb += cor_b[k] * m;
    }
    rk2[i] = su; rk2[MDIM + i] = sv; rk2[2 * MDIM + i] = sb;
}

// ---------------- tiled transpose: in (B,R,C) -> out (B,C,R) ----------------
__global__ void transpose_kernel(const float* __restrict__ in, float* __restrict__ out,
                                 int R, int C) {
    __shared__ float t[32][33];
    int b = blockIdx.z;
    int r0 = blockIdx.y * 32, c0 = blockIdx.x * 32;
    const float* ib = in + (size_t)b * R * C;
    float* ob = out + (size_t)b * R * C;
    #pragma unroll
    for (int i = threadIdx.y; i < 32; i += 8) {
        t[i][threadIdx.x] = ib[(size_t)(r0 + i) * C + c0 + threadIdx.x];
    }
    __syncthreads();
    #pragma unroll
    for (int i = threadIdx.y; i < 32; i += 8) {
        ob[(size_t)(c0 + i) * R + r0 + threadIdx.x] = t[threadIdx.x][i];
    }
}

// ---------------- LayerNorm over last dim (C=256); output tf32-rounded -------
__global__ void ln_rows_kernel(const float* __restrict__ in, float* __restrict__ out,
                               const float* __restrict__ g, const float* __restrict__ bb,
                               int rows) {
    int warp = (blockIdx.x * blockDim.x + threadIdx.x) >> 5;
    int lane = threadIdx.x & 31;
    if (warp >= rows) return;
    const float* row = in + (size_t)warp * CDIM;
    float* orow = out + (size_t)warp * CDIM;
    float v[8];
    float s = 0.f, s2 = 0.f;
    #pragma unroll
    for (int i = 0; i < 8; i++) {
        v[i] = row[lane + i * 32];
        s += v[i];
        s2 += v[i] * v[i];
    }
    #pragma unroll
    for (int o = 16; o; o >>= 1) {
        s  += __shfl_xor_sync(0xffffffffu, s,  o);
        s2 += __shfl_xor_sync(0xffffffffu, s2, o);
    }
    float mean = s * (1.f / CDIM);
    float var  = s2 * (1.f / CDIM) - mean * mean;
    float rstd = rsqrtf(var + 1e-5f);
    #pragma unroll
    for (int i = 0; i < 8; i++) {
        int c = lane + i * 32;
        orow[c] = f2tf32f((v[i] - mean) * rstd * g[c] + bb[c]);
    }
}

// ---------------- tf32 GEMM: 128x128 tile, BK=32, 3-stage cp.async ----------
// Inputs pre-rounded to tf32. A row-major [128][36] per stage (18432 B),
// B [32][136] per stage (17408 B). rk2 != null -> motion rank-2 epilogue.
__global__ __launch_bounds__(256)
void gemm_kernel(const float* __restrict__ A, const float* __restrict__ B,
                 const float* __restrict__ bias, const float* __restrict__ resid,
                 const float* __restrict__ rk2, float* __restrict__ C,
                 int M, int K, int N, int swapHalf) {
    extern __shared__ float dsm[];
    float* Asb = dsm;            // 3 * 128*36 = 13824 floats
    float* Bsb = dsm + 13824;    // 3 * 32*136 = 13056 floats
    int tid = threadIdx.x;
    int wid = tid >> 5, lane = tid & 31;
    int gid = lane >> 2, tig = lane & 3;
    int wm = wid & 1, wn = wid >> 1;
    int m0 = blockIdx.y * 128, n0 = blockIdx.x * 128;

    float acc[4][4][4] = {};

    const float* asrc[4]; unsigned adst[4];
    const float* bsrc[4]; unsigned bdst[4];
    #pragma unroll
    for (int it = 0; it < 4; it++) {
        int idx = tid + it * 256;
        int arow = idx >> 3, ac = idx & 7;
        int gm = m0 + arow, gmp = gm;
        if (swapHalf) { int b = gm / NTOK; int n = gm - b * NTOK; gmp = (b ^ 2) * NTOK + n; }
        asrc[it] = A + (size_t)gmp * K + ac * 4;
        adst[it] = (unsigned)(arow * 36 + ac * 4) * 4u;
        int brow = idx >> 5, bc = idx & 31;
        bsrc[it] = B + (size_t)brow * N + n0 + bc * 4;
        bdst[it] = (unsigned)(brow * 136 + bc * 4) * 4u;
    }
    unsigned abase = (unsigned)__cvta_generic_to_shared(Asb);
    unsigned bbase = (unsigned)__cvta_generic_to_shared(Bsb);

    int nIter = K >> 5;

    // per-stage byte strides: A = 128*36*4 = 18432, B = 32*136*4 = 17408
    #define ISSUE(st, k0) {                                                      \
        unsigned ao = abase + (unsigned)(st) * 18432u;                           \
        unsigned bo = bbase + (unsigned)(st) * 17408u;                           \
        _Pragma("unroll")                                                        \
        for (int it = 0; it < 4; it++) {                                         \
            asm volatile("cp.async.cg.shared.global [%0], [%1], 16;"             \
                         :: "r"(ao + adst[it]), "l"(asrc[it] + (k0)));           \
            asm volatile("cp.async.cg.shared.global [%0], [%1], 16;"             \
                         :: "r"(bo + bdst[it]), "l"(bsrc[it] + (size_t)(k0) * N)); \
        }                                                                        \
        asm volatile("cp.async.commit_group;");                                  \
    }

    ISSUE(0, 0);
    if (nIter > 1) { ISSUE(1, 32); }
    else { asm volatile("cp.async.commit_group;"); }

    for (int ki = 0; ki < nIter; ki++) {
        asm volatile("cp.async.wait_group 1;");
        __syncthreads();
        int s = ki - (ki / 3) * 3;
        const float* As_ = Asb + s * 4608;   // 18432 B = 4608 floats
        const float* Bs_ = Bsb + s * 4352;   // 17408 B = 4352 floats
        #pragma unroll
        for (int ks = 0; ks < 4; ks++) {
            int kb = ks * 8;
            unsigned af[4][4];
            #pragma unroll
            for (int mf = 0; mf < 4; mf++) {
                int mr = wm * 64 + mf * 16 + gid;
                af[mf][0] = __float_as_uint(As_[mr * 36 + kb + tig]);
                af[mf][1] = __float_as_uint(As_[(mr + 8) * 36 + kb + tig]);
                af[mf][2] = __float_as_uint(As_[mr * 36 + kb + tig + 4]);
                af[mf][3] = __float_as_uint(As_[(mr + 8) * 36 + kb + tig + 4]);
            }
            unsigned bf[4][2];
            #pragma unroll
            for (int nf = 0; nf < 4; nf++) {
                int nc = wn * 32 + nf * 8 + gid;
                bf[nf][0] = __float_as_uint(Bs_[(kb + tig) * 136 + nc]);
                bf[nf][1] = __float_as_uint(Bs_[(kb + tig + 4) * 136 + nc]);
            }
            #pragma unroll
            for (int mf = 0; mf < 4; mf++)
                #pragma unroll
                for (int nf = 0; nf < 4; nf++)
                    mma_tf32(acc[mf][nf], af[mf][0], af[mf][1], af[mf][2], af[mf][3],
                             bf[nf][0], bf[nf][1]);
        }
        if (ki + 2 < nIter) {
            int st = (ki + 2) - ((ki + 2) / 3) * 3;
            ISSUE(st, (ki + 2) << 5);
        } else {
            asm volatile("cp.async.commit_group;");
        }
    }
    #undef ISSUE

    // epilogue
    #pragma unroll
    for (int nf = 0; nf < 4; nf++) {
        int col = n0 + wn * 32 + nf * 8 + 2 * tig;
        float2 bi = *(const float2*)&bias[col];
        float2 wu, wv, wb;
        if (rk2) {
            wu = *(const float2*)&rk2[col];
            wv = *(const float2*)&rk2[MDIM + col];
            wb = *(const float2*)&rk2[2 * MDIM + col];
        }
        #pragma unroll
        for (int mf = 0; mf < 4; mf++) {
            #pragma unroll
            for (int r = 0; r < 2; r++) {
                int m = m0 + wm * 64 + mf * 16 + gid + 8 * r;
                float2 v = make_float2(acc[mf][nf][r * 2]     + bi.x,
                                       acc[mf][nf][r * 2 + 1] + bi.y);
                if (resid) {
                    float2 rv = *(const float2*)&resid[(size_t)m * N + col];
                    v.x += rv.x; v.y += rv.y;
                }
                if (rk2) {
                    int n = m % NTOK;
                    float cx = -1.f + 2.f * (float)(n % WW) * (1.f / 47.f);
                    float cy = -1.f + 2.f * (float)(n / WW) * (1.f / 47.f);
                    v.x -= cx * wu.x + cy * wv.x + wb.x;
                    v.y -= cx * wu.y + cy * wv.y + wb.y;
                }
                *(float2*)&C[(size_t)m * N + col] = v;
            }
        }
    }
}

// ---------------- fused flash attention + motion aggregation (tf32 mma) ----------
// No-max softmax (scores bounded); outputs tf32-rounded for downstream GEMMs.
__global__ __launch_bounds__(256)
void flash_kernel(const float* __restrict__ qb, const float* __restrict__ kvb,
                  const float* __restrict__ corw, const float* __restrict__ corb,
                  float* __restrict__ xo, float* __restrict__ cro) {
    extern __shared__ float sm[];
    float (*Ks)[36] = (float(*)[36])(sm);
    float (*Wt)[56] = (float(*)[56])(sm + 2304);
    float (*Pi)[76] = (float(*)[76])(sm + 2304 + 3584);

    int tid = threadIdx.x;
    int wid = tid >> 5, lane = tid & 31;
    int gid = lane >> 2, tig = lane & 3;
    int m0 = blockIdx.x * 128;
    int h  = blockIdx.y;
    int b  = blockIdx.z;

    const float* qbase = qb + ((size_t)b * NTOK) * CDIM + h * HD;
    const float* kbase = kvb + ((size_t)b * NTOK) * (2 * CDIM) + h * HD;
    const float* vbase = kbase + CDIM;
    const float* cwh = corw + h * MHD;
    const float* cbh = corb + h * MHD;

    unsigned qa[4][4];
    {
        size_t r0 = (size_t)(m0 + wid * 16 + gid) * CDIM;
        size_t r1 = r0 + 8 * CDIM;
        #pragma unroll
        for (int ks = 0; ks < 4; ks++) {
            qa[ks][0] = f2tf32(qbase[r0 + ks * 8 + tig]);
            qa[ks][1] = f2tf32(qbase[r1 + ks * 8 + tig]);
            qa[ks][2] = f2tf32(qbase[r0 + ks * 8 + tig + 4]);
            qa[ks][3] = f2tf32(qbase[r1 + ks * 8 + tig + 4]);
        }
    }

    float l_r[2] = {0.f, 0.f};
    float O[6][4] = {};

    int lkey = tid >> 2;
    int ld0  = (tid & 3) * 8;
    int lc0  = (tid & 3) * 4;

    float4 kR0, kR1, vR0, vR1;
    {
        const float* kr = &kbase[(size_t)lkey * (2 * CDIM) + ld0];
        kR0 = *(const float4*)kr; kR1 = *(const float4*)(kr + 4);
        const float* vr = &vbase[(size_t)lkey * (2 * CDIM) + ld0];
        vR0 = *(const float4*)vr; vR1 = *(const float4*)(vr + 4);
    }

    const int NT = NTOK / 64;
    for (int kt = 0; kt < NT; kt++) {
        int n0g = kt * 64;
        __syncthreads();
        {
            uint4 u0 = make_uint4(f2tf32(kR0.x), f2tf32(kR0.y), f2tf32(kR0.z), f2tf32(kR0.w));
            uint4 u1 = make_uint4(f2tf32(kR1.x), f2tf32(kR1.y), f2tf32(kR1.z), f2tf32(kR1.w));
            *(uint4*)&Ks[lkey][ld0]     = u0;
            *(uint4*)&Ks[lkey][ld0 + 4] = u1;
            uint4 x0 = make_uint4(f2tf32(vR0.x), f2tf32(vR0.y), f2tf32(vR0.z), f2tf32(vR0.w));
            uint4 x1 = make_uint4(f2tf32(vR1.x), f2tf32(vR1.y), f2tf32(vR1.z), f2tf32(vR1.w));
            *(uint4*)&Wt[lkey][ld0]     = x0;
            *(uint4*)&Wt[lkey][ld0 + 4] = x1;
            int kn = n0g + lkey;
            float xf = -1.f + 2.f * (float)(kn % WW) * (1.f / 47.f);
            float yf = -1.f + 2.f * (float)(kn / WW) * (1.f / 47.f);
            uint4 ce;
            ce.x = f2tf32(xf * cwh[lc0 + 0] + yf * cwh[128 + lc0 + 0] + cbh[lc0 + 0]);
            ce.y = f2tf32(xf * cwh[lc0 + 1] + yf * cwh[128 + lc0 + 1] + cbh[lc0 + 1]);
            ce.z = f2tf32(xf * cwh[lc0 + 2] + yf * cwh[128 + lc0 + 2] + cbh[lc0 + 2]);
            ce.w = f2tf32(xf * cwh[lc0 + 3] + yf * cwh[128 + lc0 + 3] + cbh[lc0 + 3]);
            *(uint4*)&Wt[lkey][32 + lc0] = ce;
        }
        __syncthreads();
        if (kt + 1 < NT) {
            const float* kr = &kbase[(size_t)(n0g + 64 + lkey) * (2 * CDIM) + ld0];
            kR0 = *(const float4*)kr; kR1 = *(const float4*)(kr + 4);
            const float* vr = &vbase[(size_t)(n0g + 64 + lkey) * (2 * CDIM) + ld0];
            vR0 = *(const float4*)vr; vR1 = *(const float4*)(vr + 4);
        }

        float c[8][4] = {};
        #pragma unroll
        for (int j = 0; j < 8; j++) {
            #pragma unroll
            for (int ks = 0; ks < 4; ks++) {
                unsigned b0 = __float_as_uint(Ks[j * 8 + gid][ks * 8 + tig]);
                unsigned b1 = __float_as_uint(Ks[j * 8 + gid][ks * 8 + tig + 4]);
                mma_tf32(c[j], qa[ks][0], qa[ks][1], qa[ks][2], qa[ks][3], b0, b1);
            }
        }

        // no-max softmax accumulation (scores bounded; exp safe)
        #pragma unroll
        for (int r = 0; r < 2; r++) {
            int prow = wid * 16 + gid + 8 * r;
            float sum = 0.f;
            #pragma unroll
            for (int j = 0; j < 8; j++) {
                float p0 = __expf(c[j][r * 2]     * SCALE);
                float p1 = __expf(c[j][r * 2 + 1] * SCALE);
                sum += p0 + p1;
                uint2 pp = make_uint2(f2tf32(p0), f2tf32(p1));
                *(uint2*)&Pi[prow][j * 8 + 2 * tig] = pp;
            }
            sum += __shfl_xor_sync(0xffffffffu, sum, 1);
            sum += __shfl_xor_sync(0xffffffffu, sum, 2);
            l_r[r] += sum;
        }
        #pragma unroll
        for (int ks = 0; ks < 8; ks++) {
            int kk = ks * 8;
            unsigned a0 = __float_as_uint(Pi[wid * 16 + gid][kk + tig]);
            unsigned a1 = __float_as_uint(Pi[wid * 16 + gid + 8][kk + tig]);
            unsigned a2 = __float_as_uint(Pi[wid * 16 + gid][kk + tig + 4]);
            unsigned a3 = __float_as_uint(Pi[wid * 16 + gid + 8][kk + tig + 4]);
            #pragma unroll
            for (int j = 0; j < 6; j++) {
                unsigned b0 = __float_as_uint(Wt[kk + tig][j * 8 + gid]);
                unsigned b1 = __float_as_uint(Wt[kk + tig + 4][j * 8 + gid]);
                mma_tf32(O[j], a0, a1, a2, a3, b0, b1);
            }
        }
    }

    #pragma unroll
    for (int r = 0; r < 2; r++) {
        float inv = 1.f / l_r[r];
        size_t gm = (size_t)b * NTOK + m0 + wid * 16 + gid + 8 * r;
        #pragma unroll
        for (int j = 0; j < 4; j++) {
            float2 ov = make_float2(f2tf32f(O[j][r * 2] * inv), f2tf32f(O[j][r * 2 + 1] * inv));
            *(float2*)&xo[gm * CDIM + h * HD + j * 8 + 2 * tig] = ov;
        }
        #pragma unroll
        for (int j = 4; j < 6; j++) {
            float2 ov = make_float2(f2tf32f(O[j][r * 2] * inv), f2tf32f(O[j][r * 2 + 1] * inv));
            *(float2*)&cro[gm * MDIM + h * MHD + (j - 4) * 8 + 2 * tig] = ov;
        }
    }
}

// ---------------- depthwise 3x3 conv + bias + exact GELU (smem row tiling) ------
__global__ __launch_bounds__(256)
void dwconv_gelu_kernel(const float* __restrict__ y, const float* __restrict__ w,
                        const float* __restrict__ bias, float* __restrict__ out) {
    __shared__ float rows[3][WW][64];
    __shared__ float wsm[64][9];
    __shared__ float bsm[64];
    int b = blockIdx.z, h = blockIdx.x, ch0 = blockIdx.y * 64;
    int tid = threadIdx.x;
    for (int i = tid; i < 64 * 9; i += 256) wsm[i / 9][i % 9] = w[(ch0 + i / 9) * 9 + i % 9];
    if (tid < 64) bsm[tid] = bias[ch0 + tid];
    const float* yb = y + (size_t)b * NTOK * HID;
    #pragma unroll
    for (int r = 0; r < 3; r++) {
        int h2 = h - 1 + r;
        if (h2 >= 0 && h2 < HH) {
            for (int idx = tid; idx < WW * 16; idx += 256) {
                int w2 = idx >> 4, c4 = (idx & 15) * 4;
                *(float4*)&rows[r][w2][c4] =
                    *(const float4*)&yb[(size_t)(h2 * WW + w2) * HID + ch0 + c4];
            }
        } else {
            for (int idx = tid; idx < WW * 16; idx += 256) {
                int w2 = idx >> 4, c4 = (idx & 15) * 4;
                *(float4*)&rows[r][w2][c4] = make_float4(0.f, 0.f, 0.f, 0.f);
            }
        }
    }
    __syncthreads();
    for (int idx = tid; idx < WW * 64; idx += 256) {
        int wc = idx >> 6, c = idx & 63;
        float acc = bsm[c];
        #pragma unroll
        for (int dh = 0; dh < 3; dh++) {
            #pragma unroll
            for (int dw = 0; dw < 3; dw++) {
                int w2 = wc + dw - 1;
                if (w2 >= 0 && w2 < WW)
                    acc += rows[dh][w2][c] * wsm[c][dh * 3 + dw];
            }
        }
        float gv = 0.5f * acc * (1.f + erff(acc * 0.70710678118654752f));
        out[((size_t)b * NTOK + h * WW + wc) * HID + ch0 + c] = f2tf32f(gv);
    }
}

// ---------------- launch ----------------
extern "C" void kernel_launch(void* const* d_in, const int* in_sizes, int n_in,
                              void* d_out, int out_size) {
    const float* feat0   = (const float*)d_in[0];
    const float* feat1   = (const float*)d_in[1];
    const float* norm1_g = (const float*)d_in[2];
    const float* norm1_b = (const float*)d_in[3];
    const float* norm2_g = (const float*)d_in[4];
    const float* norm2_b = (const float*)d_in[5];
    const float* q_w     = (const float*)d_in[6];
    const float* q_b     = (const float*)d_in[7];
    const float* kv_w    = (const float*)d_in[8];
    const float* kv_b    = (const float*)d_in[9];
    const float* cor_w   = (const float*)d_in[10];
    const float* cor_b   = (const float*)d_in[11];
    const float* mot_w   = (const float*)d_in[12];
    const float* mot_b   = (const float*)d_in[13];
    const float* proj_w  = (const float*)d_in[14];
    const float* proj_b  = (const float*)d_in[15];
    const float* fc1_w   = (const float*)d_in[16];
    const float* fc1_b   = (const float*)d_in[17];
    const float* dw_w    = (const float*)d_in[18];
    const float* dw_b    = (const float*)d_in[19];
    const float* fc2_w   = (const float*)d_in[20];
    const float* fc2_b   = (const float*)d_in[21];

    float* out_main   = (float*)d_out;
    float* out_motion = out_main + (size_t)BATCH * CDIM * NTOK;

    float *pS, *pQ, *pKV, *pXO, *pCR, *pS2, *pN2, *pY1, *pY2, *pZ, *pMO;
    float *pWQ, *pWKV, *pWP, *pW1, *pW2, *pWM, *pRK2;
    cudaGetSymbolAddress((void**)&pS,  g_S);
    cudaGetSymbolAddress((void**)&pQ,  g_Q);
    cudaGetSymbolAddress((void**)&pKV, g_KV);
    cudaGetSymbolAddress((void**)&pXO, g_XO);
    cudaGetSymbolAddress((void**)&pCR, g_CR);
    cudaGetSymbolAddress((void**)&pS2, g_S2);
    cudaGetSymbolAddress((void**)&pN2, g_N2);
    cudaGetSymbolAddress((void**)&pY1, g_Y1);
    cudaGetSymbolAddress((void**)&pY2, g_Y2);
    cudaGetSymbolAddress((void**)&pZ,  g_Z);
    cudaGetSymbolAddress((void**)&pMO, g_MO);
    cudaGetSymbolAddress((void**)&pWQ,  g_WQ);
    cudaGetSymbolAddress((void**)&pWKV, g_WKV);
    cudaGetSymbolAddress((void**)&pWP,  g_WP);
    cudaGetSymbolAddress((void**)&pW1,  g_W1);
    cudaGetSymbolAddress((void**)&pW2,  g_W2);
    cudaGetSymbolAddress((void**)&pWM,  g_WM);
    cudaGetSymbolAddress((void**)&pRK2, g_RK2);

    dim3 tb(32, 8);

    // prepass: round weights to tf32, compute rank-2 motion correction
    round_weights_kernel<<<784, 256>>>((const float4*)q_w, (const float4*)kv_w,
                                       (const float4*)proj_w, (const float4*)fc1_w,
                                       (const float4*)fc2_w, (const float4*)mot_w,
                                       (float4*)pWQ, (float4*)pWKV, (float4*)pWP,
                                       (float4*)pW1, (float4*)pW2, (float4*)pWM);
    rk2_kernel<<<1, 128>>>(cor_w, cor_b, mot_w, pRK2);

    transpose_kernel<<<dim3(NTOK / 32, CDIM / 32, 2), tb>>>(feat0, pS, CDIM, NTOK);
    transpose_kernel<<<dim3(NTOK / 32, CDIM / 32, 2), tb>>>(feat1, pS + 2 * (size_t)NTOK * CDIM, CDIM, NTOK);
    ln_rows_kernel<<<(BATCH * NTOK) / 8, 256>>>(pS, pS, norm1_g, norm1_b, BATCH * NTOK);

    int M = BATCH * NTOK;
    size_t gsmem = 26880 * sizeof(float);   // 107520 B (3-stage cp.async)
    cudaFuncSetAttribute(gemm_kernel, cudaFuncAttributeMaxDynamicSharedMemorySize, (int)gsmem);

    gemm_kernel<<<dim3(CDIM / 128, M / 128), 256, gsmem>>>(pS, pWQ, q_b, nullptr, nullptr, pQ,
                                                           M, CDIM, CDIM, 0);
    gemm_kernel<<<dim3(2 * CDIM / 128, M / 128), 256, gsmem>>>(pS, pWKV, kv_b, nullptr, nullptr, pKV,
                                                               M, CDIM, 2 * CDIM, 1);
    size_t fsmem = (2304 + 3584 + 128 * 76) * sizeof(float);   // 62464 B
    cudaFuncSetAttribute(flash_kernel, cudaFuncAttributeMaxDynamicSharedMemorySize, (int)fsmem);
    flash_kernel<<<dim3(NTOK / 128, NHEAD, BATCH), 256, fsmem>>>(pQ, pKV, cor_w, cor_b, pXO, pCR);
    gemm_kernel<<<dim3(CDIM / 128, M / 128), 256, gsmem>>>(pXO, pWP, proj_b, pS, nullptr, pS2,
                                                           M, CDIM, CDIM, 0);
    ln_rows_kernel<<<(BATCH * NTOK) / 8, 256>>>(pS2, pN2, norm2_g, norm2_b, BATCH * NTOK);
    gemm_kernel<<<dim3(HID / 128, M / 128), 256, gsmem>>>(pN2, pW1, fc1_b, nullptr, nullptr, pY1,
                                                          M, CDIM, HID, 0);
    dwconv_gelu_kernel<<<dim3(HH, HID / 64, BATCH), 256>>>(pY1, dw_w, dw_b, pY2);
    gemm_kernel<<<dim3(CDIM / 128, M / 128), 256, gsmem>>>(pY2, pW2, fc2_b, pS2, nullptr, pZ,
                                                           M, HID, CDIM, 0);
    gemm_kernel<<<dim3(MDIM / 128, M / 128), 256, gsmem>>>(pCR, pWM, mot_b, nullptr, pRK2, pMO,
                                                           M, MDIM, MDIM, 0);
    transpose_kernel<<<dim3(CDIM / 32, NTOK / 32, BATCH), tb>>>(pZ, out_main, NTOK, CDIM);
    transpose_kernel<<<dim3(MDIM / 32, NTOK / 32, BATCH), tb>>>(pMO, out_motion, NTOK, MDIM);
}